// round 17
// baseline (speedup 1.0000x reference)
#include <cuda_runtime.h>
#include <math.h>
#include <stdint.h>

// ---------------- problem constants (IMG 800x1024, strides 8..128) ----------
#define NBATCH 16
#define NCLS   80
#define TOPN   300
#define NREAL  1500
#define NWORDS 47            // ceil(1504/32)
#define POST   100
#define CAP    4096          // survivor cap per (level,batch) pair

__constant__ int c_HW[5]   = {12800, 3200, 800, 208, 56};
__constant__ int c_CHW[5]  = {1024000, 256000, 64000, 16640, 4480};
__constant__ int c_LOFF[5] = {0, 204800, 256000, 268800, 272128};
__constant__ int c_R[5]    = {40, 80, 300, 300, 300};
__constant__ int c_BPP[5]  = {250, 63, 16, 5, 2};
__constant__ int c_BOFF[5] = {0, 4000, 5008, 5264, 5344};
#define NBLOCKS_COLLECT 5376
#define SCTR_TOTAL 273024

// dynamic smem layout for k_final
#define OFF_SKEYS 0          // u64[4096]   32768
#define OFF_CKEY  32768      // u64[1504]   12032
#define OFF_OB    44800      // float4[1504] 24064
#define OFF_SA    68864      // float[1504]  6016
#define OFF_HIST  74880      // u32[1024]    4096
#define OFF_PART  78976      // u32[1024]    4096
#define OFF_SSORT 83072      // u16[1504]    3008
#define OFF_SLIST 86080      // int[128]      512
#define SMEM_FINAL 86592

// ---------------- device scratch (static, allocation-free) ------------------
__device__ float    g_sctr[SCTR_TOTAL];      // exact sigmoid(ctr)
__device__ float    g_L[SCTR_TOTAL];         // per-position logit threshold
__device__ unsigned g_hist1[80 * 2048];
__device__ unsigned g_scnt[80];
__device__ unsigned long long g_surv[(size_t)80 * CAP];

struct InPtrs {
    const float* loc[5];
    const float* cls[5];
    const float* box[5];
    const float* ctr[5];
};

__device__ __forceinline__ float sigm(float x) { return 1.0f / (1.0f + expf(-x)); }

__device__ __forceinline__ float approx_rcp(float d) {
    float r = __int_as_float(0x7EF311C3 - __float_as_int(d));
    r = r * (2.0f - d * r);
    r = r * (2.0f - d * r);
    return r;
}
// MUFU-free approx sigmoid (sampling only), |rel err| <= ~0.25%
__device__ __forceinline__ float approx_a(float cv, float sv) {
    float t = fminf(cv, 60.0f) * -1.44269504f;
    float fl = floorf(t);
    float f = t - fl;
    float p2 = fmaf(fmaf(0.33718944f, f, 0.65763628f), f, 1.0017247f);
    float z = p2 * __int_as_float(((int)fl + 127) << 23);
    return approx_rcp(1.0f + z) * sv;
}

__device__ __forceinline__ void map_block(int bid, int& l, int& b, int& chunk) {
    if (bid < 4000)      l = 0;
    else if (bid < 5008) l = 1;
    else if (bid < 5264) l = 2;
    else if (bid < 5344) l = 3;
    else                 l = 4;
    int rel = bid - c_BOFF[l];
    b = rel / c_BPP[l];
    chunk = rel % c_BPP[l];
}

// monotone 1024-bin key for score-prune (hi in [0x80000000, 0xBF800000])
__device__ __forceinline__ int keybin(unsigned hi) {
    int d = (int)(hi - 0xBD000000u);
    d >>= 16;
    return min(1023, max(d, 0));
}

// ---------------- kernel 1: zero scratch + exact sigmoid(ctr) [R16-proven] ---
__global__ __launch_bounds__(256) void k_init(InPtrs P) {
    int i = blockIdx.x * 256 + threadIdx.x;
    if (i < 80 * 2048) g_hist1[i] = 0;
    if (i < 80) g_scnt[i] = 0;
    if (i < SCTR_TOTAL) {
        int l = (i < 204800) ? 0 : (i < 256000) ? 1 : (i < 268800) ? 2 : (i < 272128) ? 3 : 4;
        g_sctr[i] = sigm(P.ctr[l][i - c_LOFF[l]]);
    }
}

// ---------------- kernel 2: sampled approx-score histogram [R16-proven] ------
__global__ __launch_bounds__(256) void k_sample(InPtrs P) {
    __shared__ unsigned hist[2048];
    for (int i = threadIdx.x; i < 2048; i += 256) hist[i] = 0;
    __syncthreads();
    int bid = blockIdx.x;
    int l, b, sub, nsub, stride;
    if (bid < 128)      { l = 0; b = bid >> 3; sub = bid & 7; nsub = 8; stride = 32; }
    else if (bid < 160) { l = 1; b = (bid - 128) >> 1; sub = (bid - 128) & 1; nsub = 2; stride = 8; }
    else if (bid < 176) { l = 2; b = bid - 160; sub = 0; nsub = 1; stride = 1; }
    else if (bid < 192) { l = 3; b = bid - 176; sub = 0; nsub = 1; stride = 1; }
    else                { l = 4; b = bid - 192; sub = 0; nsub = 1; stride = 1; }
    int chw4 = c_CHW[l] >> 2;
    int per = chw4 / nsub;
    int hw = c_HW[l];
    const float4* cls4 = (const float4*)(P.cls[l]) + (size_t)b * chw4 + (size_t)sub * per;
    const float4* sctr4 = (const float4*)(g_sctr + c_LOFF[l] + b * hw);
    int base_e = sub * per * 4;
    for (int i4 = threadIdx.x * stride; i4 < per; i4 += 256 * stride) {
        float4 v = cls4[i4];
        int e = base_e + (i4 << 2);
        int pos0 = e % hw;
        float4 s4 = sctr4[pos0 >> 2];
        float vv[4] = {v.x, v.y, v.z, v.w};
        float ss[4] = {s4.x, s4.y, s4.z, s4.w};
        #pragma unroll
        for (int k = 0; k < 4; k++) {
            float cv = vv[k];
            if (cv < -2.945f) continue;
            float a = approx_a(cv, ss[k]);
            atomicAdd(&hist[min(2047, (int)(a * 2048.0f))], 1u);
        }
    }
    __syncthreads();
    int p = l * 16 + b;
    for (int i = threadIdx.x; i < 2048; i += 256)
        if (hist[i]) atomicAdd(&g_hist1[p * 2048 + i], hist[i]);
}

// ---------------- kernel 3: threshold -> per-position logit L [R16-proven] ---
__global__ __launch_bounds__(256) void k_threshL() {
    __shared__ unsigned sh[2048];
    __shared__ unsigned part[256];
    __shared__ float s_thr;
    int p = blockIdx.x, t = threadIdx.x;
    if (t == 0) s_thr = 0.0f;
    unsigned R = (unsigned)c_R[p / 16];
    const unsigned* h = g_hist1 + (size_t)p * 2048;
    unsigned lsum = 0;
    for (int i = 0; i < 8; i++) { unsigned v = h[t * 8 + i]; sh[t * 8 + i] = v; lsum += v; }
    part[t] = lsum;
    __syncthreads();
    for (int off = 1; off < 256; off <<= 1) {
        unsigned o = (t + off < 256) ? part[t + off] : 0u;
        __syncthreads();
        part[t] += o;
        __syncthreads();
    }
    unsigned cum = (t < 255) ? part[t + 1] : 0u;
    for (int i = 7; i >= 0; i--) {
        int bidx = t * 8 + i;
        unsigned hv = sh[bidx];
        if (cum < R && cum + hv >= R)
            s_thr = (float)bidx * (1.0f / 2048.0f) * 0.985f;
        cum += hv;
    }
    __syncthreads();
    float thr = s_thr;
    int l = p / 16, b = p % 16;
    int hw = c_HW[l];
    int base = c_LOFF[l] + b * hw;
    for (int i = t; i < hw; i += 256) {
        float sv = g_sctr[base + i];
        float L;
        if (thr <= 0.0f) L = -2.944f;
        else {
            float x = thr / sv;
            if (x >= 1.0f) L = 1e30f;
            else L = fmaxf(logf(x / (1.0f - x)) - 0.02f, -2.944f);
        }
        g_L[base + i] = L;
    }
}

// ---------------- kernel 4: full sweep [R16-proven float4 body] --------------
template <int HW>
__device__ __forceinline__ void collect_body(const float4* cls4, const float4* Lv,
                                             const float* sctr, int start, int chw, int p) {
    int e4end = min(start + 4096, chw) >> 2;
    for (int e4 = (start >> 2) + threadIdx.x; e4 < e4end; e4 += 256) {
        float4 v = cls4[e4];
        int e = e4 << 2;
        int c0 = e / HW;
        int pos0 = e - c0 * HW;
        float4 L4 = Lv[pos0 >> 2];
        float vv[4] = {v.x, v.y, v.z, v.w};
        float LL[4] = {L4.x, L4.y, L4.z, L4.w};
        #pragma unroll
        for (int k = 0; k < 4; k++) {
            float cv = vv[k];
            if (cv < LL[k]) continue;
            float se = sigm(cv);              // exact path, rare
            if (se <= 0.05f) continue;
            float sv = sctr[pos0 + k];
            float m = se * sv;
            unsigned key32 = __float_as_uint(m) | 0x80000000u;
            unsigned idx = (unsigned)((pos0 + k) * NCLS + c0);
            unsigned long long key = ((unsigned long long)key32 << 32) | (unsigned)(~idx);
            unsigned slot = atomicAdd(&g_scnt[p], 1u);
            if (slot < CAP) g_surv[(size_t)p * CAP + slot] = key;
        }
    }
}

__global__ __launch_bounds__(256) void k_collect(InPtrs P) {
    int l, b, chunk; map_block(blockIdx.x, l, b, chunk);
    int p = l * 16 + b;
    int start = chunk * 4096;
    switch (l) {
    case 0: collect_body<12800>((const float4*)(P.cls[0] + (size_t)b * 1024000),
            (const float4*)(g_L + 0 + b * 12800), g_sctr + 0 + b * 12800, start, 1024000, p); break;
    case 1: collect_body<3200>((const float4*)(P.cls[1] + (size_t)b * 256000),
            (const float4*)(g_L + 204800 + b * 3200), g_sctr + 204800 + b * 3200, start, 256000, p); break;
    case 2: collect_body<800>((const float4*)(P.cls[2] + (size_t)b * 64000),
            (const float4*)(g_L + 256000 + b * 800), g_sctr + 256000 + b * 800, start, 64000, p); break;
    case 3: collect_body<208>((const float4*)(P.cls[3] + (size_t)b * 16640),
            (const float4*)(g_L + 268800 + b * 208), g_sctr + 268800 + b * 208, start, 16640, p); break;
    case 4: collect_body<56>((const float4*)(P.cls[4] + (size_t)b * 4480),
            (const float4*)(g_L + 272128 + b * 56), g_sctr + 272128 + b * 56, start, 4480, p); break;
    }
}

// ---------------- kernel 5: fused select + rank + lazy NMS + emit ------------
__global__ __launch_bounds__(1024) void k_final(InPtrs P, float* out) {
    extern __shared__ __align__(16) unsigned char dyn[];
    unsigned long long* skeys = (unsigned long long*)(dyn + OFF_SKEYS);
    unsigned long long* ckey  = (unsigned long long*)(dyn + OFF_CKEY);
    float4* ob = (float4*)(dyn + OFF_OB);
    float*  sa = (float*)(dyn + OFF_SA);
    unsigned* hist = (unsigned*)(dyn + OFF_HIST);
    unsigned* part = (unsigned*)(dyn + OFF_PART);
    unsigned short* ssort = (unsigned short*)(dyn + OFF_SSORT);
    int* slist = (int*)(dyn + OFF_SLIST);
    __shared__ int s_cnt2, s_B, s_cnt;
    int b = blockIdx.x, t = threadIdx.x;

    // ---- per-level exact top-300 (R16 select transplant, 1024 threads) ----
    for (int l = 0; l < 5; l++) {
        int p = l * 16 + b;
        int n = min((int)g_scnt[p], CAP);
        const unsigned long long* sv = g_surv + (size_t)p * CAP;
        int m = n;
        bool pruned = false;
        if (n > 1024) {
            hist[t] = 0;
            if (t == 0) { s_cnt2 = 0; s_B = 0; }
            __syncthreads();
            for (int i = t; i < n; i += 1024)
                atomicAdd(&hist[keybin((unsigned)(sv[i] >> 32))], 1u);
            __syncthreads();
            part[t] = hist[t];
            __syncthreads();
            for (int off = 1; off < 1024; off <<= 1) {
                unsigned o = (t + off < 1024) ? part[t + off] : 0u;
                __syncthreads();
                part[t] += o;
                __syncthreads();
            }
            unsigned cum = (t < 1023) ? part[t + 1] : 0u;   // strictly above bin t
            if (cum < 300u && cum + hist[t] >= 300u) s_B = t;
            __syncthreads();
            int B = s_B;
            for (int i = t; i < n; i += 1024) {
                unsigned long long key = sv[i];
                if (keybin((unsigned)(key >> 32)) >= B) {
                    int idx = atomicAdd(&s_cnt2, 1);
                    if (idx < CAP) skeys[idx] = key;
                }
            }
            __syncthreads();
            if (s_cnt2 <= 1024) { m = s_cnt2; pruned = true; }
        }
        int P2 = 1024; while (P2 < m) P2 <<= 1;              // <= 4096
        for (int i = t; i < P2; i += 1024) {
            if (i < m) { if (!pruned) skeys[i] = sv[i]; }
            else skeys[i] = 0ull;
        }
        __syncthreads();
        for (int k2 = 2; k2 <= P2; k2 <<= 1)
            for (int j = k2 >> 1; j > 0; j >>= 1) {
                for (int i = t; i < P2; i += 1024) {
                    int ix = i ^ j;
                    if (ix > i) {
                        bool up = ((i & k2) == 0);
                        unsigned long long a = skeys[i], c = skeys[ix];
                        if (up ? (a < c) : (a > c)) { skeys[i] = c; skeys[ix] = a; }
                    }
                }
                __syncthreads();
            }
        if (t < TOPN) {
            int slot = l * TOPN + t;
            bool valid = false;
            if (t < m) {
                unsigned long long key = skeys[t];
                unsigned hi = (unsigned)(key >> 32);
                if (hi > 0x80000000u) {
                    valid = true;
                    unsigned idx = ~(unsigned)(key & 0xFFFFFFFFu);
                    int pos = (int)(idx / NCLS), c = (int)(idx % NCLS);
                    int hw = c_HW[l];
                    const float* bx = P.box[l] + (size_t)b * 4 * hw;
                    float bl = bx[pos], bt2 = bx[hw + pos], br = bx[2 * hw + pos], bbo = bx[3 * hw + pos];
                    float lx = P.loc[l][2 * pos], ly = P.loc[l][2 * pos + 1];
                    float x1 = fminf(fmaxf(lx - bl, 0.f), 1023.f);
                    float y1 = fminf(fmaxf(ly - bt2, 0.f), 799.f);
                    float x2 = fminf(fmaxf(lx + br, 0.f), 1023.f);
                    float y2 = fminf(fmaxf(ly + bbo, 0.f), 799.f);
                    float off = (float)(c + 1) * 1025.0f;
                    float4 obv = make_float4(x1 + off, y1 + off, x2 + off, y2 + off);
                    ob[slot] = obv;
                    sa[slot] = (obv.z - obv.x) * (obv.w - obv.y);
                    ckey[slot] = ((unsigned long long)hi << 32) |
                                 (unsigned)(~(((unsigned)l << 20) | idx));
                }
            }
            if (!valid) {
                ob[slot] = make_float4(0.f, 0.f, 0.f, 0.f);
                sa[slot] = 0.f;
                ckey[slot] = (unsigned long long)(NREAL - 1 - slot);  // distinct, descending tail
            }
        }
        __syncthreads();
    }

    // ---- global rank via 5 binary searches over descending blocks [R16] ----
    #pragma unroll
    for (int half = 0; half < 2; half++) {
        int i = t + half * 1024;
        if (i >= NREAL) break;
        unsigned long long x = ckey[i];
        int rank = 0;
        #pragma unroll
        for (int mm = 0; mm < 5; mm++) {
            const unsigned long long* arr = ckey + mm * TOPN;
            int lo = 0, hi2 = TOPN;
            while (lo < hi2) {
                int mid = (lo + hi2) >> 1;
                if (arr[mid] > x) lo = mid + 1; else hi2 = mid;
            }
            rank += lo;
        }
        ssort[rank] = (unsigned short)i;   // permutation: no conflicts
    }
    __syncthreads();

    // ---- lazy greedy NMS — warp 0, slot indirection (broadcast LDS) [R15] ----
    if (t < 32) {
        int cnt = 0;
        for (int w = 0; w < NWORDS && cnt < POST; w++) {
            int r = (w << 5) + t;
            float4 bi; float ai; bool valid;
            if (r < NREAL) {
                int si = (int)ssort[r];
                bi = ob[si]; ai = sa[si];
                valid = ckey[si] > 0xFFFFFFFFull;
            } else {
                bi = make_float4(0.f, 0.f, 0.f, 0.f); ai = 0.f; valid = false;
            }
            bool sup = false;
            for (int k = 0; k < cnt; k++) {
                int kk = slist[k];                  // slot of kept box
                float4 bk = ob[kk];                 // broadcast LDS
                float iw = fminf(bi.z, bk.z) - fmaxf(bi.x, bk.x);
                float ih = fminf(bi.w, bk.w) - fmaxf(bi.y, bk.y);
                float inter = fmaxf(iw, 0.f) * fmaxf(ih, 0.f);
                float uni = fmaxf(ai + sa[kk] - inter, 1e-9f);
                sup |= inter > 0.6f * uni;
            }
            unsigned supin = 0;
            #pragma unroll 8
            for (int j = 0; j < 32; j++) {
                int rj = (w << 5) + j;
                float4 bj; float aj;
                if (rj < NREAL) {
                    int sj = (int)ssort[rj];        // broadcast LDS
                    bj = ob[sj]; aj = sa[sj];
                } else {
                    bj = make_float4(0.f, 0.f, 0.f, 0.f); aj = 0.f;
                }
                float iw = fminf(bi.z, bj.z) - fmaxf(bi.x, bj.x);
                float ih = fminf(bi.w, bj.w) - fmaxf(bi.y, bj.y);
                float inter = fmaxf(iw, 0.f) * fmaxf(ih, 0.f);
                float uni = fmaxf(ai + aj - inter, 1e-9f);
                if (inter > 0.6f * uni && j != t) supin |= 1u << j;
            }
            unsigned alive = __ballot_sync(0xffffffffu, valid && !sup);
            while (alive && cnt < POST) {
                int bit = __ffs(alive) - 1;
                slist[cnt] = (int)ssort[(w << 5) + bit];
                cnt++;
                unsigned supnow = __ballot_sync(0xffffffffu, (supin >> bit) & 1u);
                alive &= ~supnow & ~(1u << bit);
            }
        }
        if (t == 0) s_cnt = cnt;
    }
    __syncthreads();

    // ---- emit: re-decode kept from ckey (identical fp ops) ----
    int cnt = s_cnt;
    float* o5 = out + (size_t)b * POST * 5;
    float* ol = out + NBATCH * POST * 5 + b * POST;
    float* ov = out + NBATCH * POST * 5 + NBATCH * POST + b * POST;
    for (int k = t; k < POST; k += 1024) {
        float b0 = 0.f, b1 = 0.f, b2 = 0.f, b3 = 0.f, sc = 0.f, lab = 0.f, val = 0.f;
        if (k < cnt) {
            int slot = slist[k];
            unsigned long long key = ckey[slot];
            unsigned hi = (unsigned)(key >> 32);
            unsigned li = ~(unsigned)(key & 0xFFFFFFFFu);
            int l = (int)(li >> 20);
            unsigned idx = li & 0xFFFFFu;
            int pos = (int)(idx / NCLS), c = (int)(idx % NCLS);
            int hw = c_HW[l];
            const float* bxp = P.box[l] + (size_t)b * 4 * hw;
            float bl = bxp[pos], bt2 = bxp[hw + pos], br = bxp[2 * hw + pos], bbo = bxp[3 * hw + pos];
            float lx = P.loc[l][2 * pos], ly = P.loc[l][2 * pos + 1];
            b0 = fminf(fmaxf(lx - bl, 0.f), 1023.f);
            b1 = fminf(fmaxf(ly - bt2, 0.f), 799.f);
            b2 = fminf(fmaxf(lx + br, 0.f), 1023.f);
            b3 = fminf(fmaxf(ly + bbo, 0.f), 799.f);
            float msc = __uint_as_float(hi ^ 0x80000000u);
            sc = sqrtf(fmaxf(msc, 1e-12f));
            lab = (float)(c + 1);
            val = 1.0f;
        }
        o5[k * 5 + 0] = b0; o5[k * 5 + 1] = b1;
        o5[k * 5 + 2] = b2; o5[k * 5 + 3] = b3;
        o5[k * 5 + 4] = sc;
        ol[k] = lab; ov[k] = val;
    }
}

// ---------------- launch ------------------------------------------------------
extern "C" void kernel_launch(void* const* d_in, const int* in_sizes, int n_in,
                              void* d_out, int out_size) {
    InPtrs P;
    bool sig_order = (n_in < 2) || (in_sizes[1] == 6400);
    for (int l = 0; l < 5; l++) {
        if (sig_order) {
            P.loc[l] = (const float*)d_in[l];
            P.cls[l] = (const float*)d_in[5 + l];
            P.box[l] = (const float*)d_in[10 + l];
            P.ctr[l] = (const float*)d_in[15 + l];
        } else {
            P.loc[l] = (const float*)d_in[4 * l + 0];
            P.cls[l] = (const float*)d_in[4 * l + 1];
            P.box[l] = (const float*)d_in[4 * l + 2];
            P.ctr[l] = (const float*)d_in[4 * l + 3];
        }
    }
    cudaFuncSetAttribute(k_final, cudaFuncAttributeMaxDynamicSharedMemorySize, SMEM_FINAL);
    k_init<<<(SCTR_TOTAL + 255) / 256, 256>>>(P);          // 1: zero + sctr
    k_sample<<<208, 256>>>(P);                             // 2: sampled hist
    k_threshL<<<80, 256>>>();                              // 3: threshold -> logit L
    k_collect<<<NBLOCKS_COLLECT, 256>>>(P);                // 4: R16 sweep
    k_final<<<NBATCH, 1024, SMEM_FINAL>>>(P, (float*)d_out); // 5: select+rank+NMS+emit
}